// round 2
// baseline (speedup 1.0000x reference)
#include <cuda_runtime.h>
#include <cstdint>

#define NB    32
#define CIN   128
#define TLEN  4096
#define KBR   4
#define COUT  256
#define KS    7
#define PADL  3

// conv tiling
#define TT    128     // t tile
#define COTILE 128    // cout tile
#define CICH  8       // ci chunk
#define XROW  144     // ull slots per ci row (134 + skew room)

// ---------------- scratch (device globals; no runtime allocation) ----------
__device__ float g_pooled[NB * CIN];
__device__ float g_alpha[NB * KBR];
__device__ float g_weff[(size_t)NB * CIN * KS * COUT];   // [b][ci*7+s][co], ~29.4MB

// ---------------- packed fp32x2 FMA ----------------------------------------
__device__ __forceinline__ void fma2(unsigned long long &d,
                                     unsigned long long a,
                                     unsigned long long b) {
    asm("fma.rn.f32x2 %0, %1, %2, %0;" : "+l"(d) : "l"(a), "l"(b));
}

// ---------------- 1) pooled mean over T ------------------------------------
__global__ void pool_kernel(const float* __restrict__ x) {
    int row = blockIdx.x;                       // b*CIN + ci
    const float4* xr = reinterpret_cast<const float4*>(x + (size_t)row * TLEN);
    float s = 0.f;
    for (int i = threadIdx.x; i < TLEN / 4; i += blockDim.x) {
        float4 v = xr[i];
        s += (v.x + v.y) + (v.z + v.w);
    }
    __shared__ float sm[8];
    int lane = threadIdx.x & 31, wrp = threadIdx.x >> 5;
    #pragma unroll
    for (int o = 16; o; o >>= 1) s += __shfl_down_sync(0xffffffffu, s, o);
    if (lane == 0) sm[wrp] = s;
    __syncthreads();
    if (threadIdx.x == 0) {
        float v = 0.f;
        int nw = blockDim.x >> 5;
        for (int i = 0; i < nw; i++) v += sm[i];
        g_pooled[row] = v * (1.0f / TLEN);
    }
}

// ---------------- 2) routing softmax ----------------------------------------
__global__ void alpha_kernel(const float* __restrict__ rw,
                             const float* __restrict__ rb) {
    int b = blockIdx.x, tid = threadIdx.x;      // 128 threads
    float p = g_pooled[b * CIN + tid];
    __shared__ float part[KBR][4];
    int lane = tid & 31, wrp = tid >> 5;
    #pragma unroll
    for (int k = 0; k < KBR; k++) {
        float v = p * rw[k * CIN + tid];
        #pragma unroll
        for (int o = 16; o; o >>= 1) v += __shfl_down_sync(0xffffffffu, v, o);
        if (lane == 0) part[k][wrp] = v;
    }
    __syncthreads();
    if (tid == 0) {
        float sc[KBR], m = -1e30f;
        #pragma unroll
        for (int k = 0; k < KBR; k++) {
            sc[k] = part[k][0] + part[k][1] + part[k][2] + part[k][3] + rb[k];
            m = fmaxf(m, sc[k]);
        }
        float den = 0.f;
        #pragma unroll
        for (int k = 0; k < KBR; k++) { sc[k] = __expf(sc[k] - m); den += sc[k]; }
        float inv = 1.0f / den;
        #pragma unroll
        for (int k = 0; k < KBR; k++) g_alpha[b * KBR + k] = sc[k] * inv;
    }
}

// ---------------- 3) fold alpha into weights: W_eff -------------------------
// g_weff[b][cis][co], cis = ci*7+s, co contiguous (256)
__global__ void weff_kernel(const float* __restrict__ w) {
    int b = blockIdx.x;
    float a0 = g_alpha[b * KBR + 0];
    float a1 = g_alpha[b * KBR + 1];
    float a2 = g_alpha[b * KBR + 2];
    float a3 = g_alpha[b * KBR + 3];
    int cis0 = blockIdx.y * 32;
    int co = threadIdx.x;                      // 256 threads
    const int KSTRIDE = COUT * CIN * KS;
    for (int r = 0; r < 32; r++) {
        int cis = cis0 + r;
        int ci = cis / 7, s = cis - ci * 7;
        int off = (co * CIN + ci) * KS + s;    // weight[k][co][ci][s]
        float v = a0 * w[off]
                + a1 * w[off + KSTRIDE]
                + a2 * w[off + 2 * KSTRIDE]
                + a3 * w[off + 3 * KSTRIDE];
        g_weff[((size_t)b * (CIN * KS) + cis) * COUT + co] = v;
    }
}

// ---------------- 4) routed conv as implicit GEMM (f32x2) -------------------
// block tile: COTILE=128 x TT=128 for one batch. 256 threads = 16(ty) x 16(tx),
// each thread: 8 cout x 8 t, accumulated as 4 f32x2-pairs-along-co x 8 t.
__global__ __launch_bounds__(256, 2)
void conv_kernel(const float* __restrict__ x,
                 const float* __restrict__ bias,
                 float* __restrict__ out) {
    __shared__ unsigned long long xd[CICH * XROW];      // x duplicated (v,v), skewed
    __shared__ float wsm[CICH * KS * COTILE];           // W_eff chunk

    int b   = blockIdx.z;
    int co0 = blockIdx.y * COTILE;
    int t0  = blockIdx.x * TT;
    int tid = threadIdx.x;
    int tx = tid & 15, ty = tid >> 4;
    int myco = co0 + ty * 8;
    int myt  = t0 + tx * 8;

    unsigned long long acc[32];
    #pragma unroll
    for (int i = 0; i < 32; i++) acc[i] = 0ull;

    const float* xb = x + (size_t)b * CIN * TLEN;
    const float* wb = g_weff + (size_t)b * (CIN * KS) * COUT;

    for (int cc = 0; cc < CIN; cc += CICH) {
        __syncthreads();
        // stage x rows [cc..cc+7], local i in [0,134): t = t0-3+i, duplicated pair
        for (int idx = tid; idx < CICH * 134; idx += 256) {
            int r = idx / 134, i = idx - r * 134;
            int tg = t0 - PADL + i;
            float v = (tg >= 0 && tg < TLEN) ? xb[(cc + r) * TLEN + tg] : 0.f;
            unsigned int ub = __float_as_uint(v);
            xd[r * XROW + i + (i >> 4)] = ((unsigned long long)ub << 32) | ub;
        }
        // stage W_eff rows cis = cc*7 .. cc*7+55, cols co0..co0+127
        for (int idx = tid; idx < 56 * 32; idx += 256) {
            int r = idx >> 5, c4 = idx & 31;
            float4 v = *reinterpret_cast<const float4*>(
                &wb[(size_t)(cc * 7 + r) * COUT + co0 + c4 * 4]);
            *reinterpret_cast<float4*>(&wsm[r * COTILE + c4 * 4]) = v;
        }
        __syncthreads();

        #pragma unroll
        for (int r = 0; r < CICH; r++) {
            unsigned long long bd[14];
            #pragma unroll
            for (int j = 0; j < 14; j++) {
                int i = tx * 8 + j;
                bd[j] = xd[r * XROW + i + (i >> 4)];
            }
            #pragma unroll
            for (int s = 0; s < KS; s++) {
                const unsigned long long* wrow =
                    reinterpret_cast<const unsigned long long*>(
                        &wsm[(r * KS + s) * COTILE]) + ty * 4;
                unsigned long long a0 = wrow[0];
                unsigned long long a1 = wrow[1];
                unsigned long long a2 = wrow[2];
                unsigned long long a3 = wrow[3];
                #pragma unroll
                for (int j = 0; j < 8; j++) {
                    unsigned long long bv = bd[s + j];
                    fma2(acc[0 * 8 + j], a0, bv);
                    fma2(acc[1 * 8 + j], a1, bv);
                    fma2(acc[2 * 8 + j], a2, bv);
                    fma2(acc[3 * 8 + j], a3, bv);
                }
            }
        }
    }

    // epilogue: + bias_eff, store (2 channels per f32x2 pair)
    float al0 = g_alpha[b * KBR + 0], al1 = g_alpha[b * KBR + 1];
    float al2 = g_alpha[b * KBR + 2], al3 = g_alpha[b * KBR + 3];
    #pragma unroll
    for (int c2 = 0; c2 < 4; c2++) {
        int clo = myco + 2 * c2;
        int chi = clo + 1;
        float belo = al0 * bias[0 * COUT + clo] + al1 * bias[1 * COUT + clo]
                   + al2 * bias[2 * COUT + clo] + al3 * bias[3 * COUT + clo];
        float behi = al0 * bias[0 * COUT + chi] + al1 * bias[1 * COUT + chi]
                   + al2 * bias[2 * COUT + chi] + al3 * bias[3 * COUT + chi];
        float lo[8], hi[8];
        #pragma unroll
        for (int j = 0; j < 8; j++) {
            unsigned long long v = acc[c2 * 8 + j];
            lo[j] = __uint_as_float((unsigned int)v) + belo;
            hi[j] = __uint_as_float((unsigned int)(v >> 32)) + behi;
        }
        float* plo = out + ((size_t)b * COUT + clo) * TLEN + myt;
        float* phi = plo + TLEN;
        *reinterpret_cast<float4*>(plo)     = make_float4(lo[0], lo[1], lo[2], lo[3]);
        *reinterpret_cast<float4*>(plo + 4) = make_float4(lo[4], lo[5], lo[6], lo[7]);
        *reinterpret_cast<float4*>(phi)     = make_float4(hi[0], hi[1], hi[2], hi[3]);
        *reinterpret_cast<float4*>(phi + 4) = make_float4(hi[4], hi[5], hi[6], hi[7]);
    }
}

// ---------------- launch -----------------------------------------------------
extern "C" void kernel_launch(void* const* d_in, const int* in_sizes, int n_in,
                              void* d_out, int out_size) {
    const float* x    = (const float*)d_in[0];   // [32,128,4096]
    const float* w    = (const float*)d_in[1];   // [4,256,128,7]
    const float* bias = (const float*)d_in[2];   // [4,256]
    const float* rw   = (const float*)d_in[3];   // [4,128]
    const float* rb   = (const float*)d_in[4];   // [4]
    float* out = (float*)d_out;                  // [32,256,4096]

    pool_kernel <<<NB * CIN, 256>>>(x);
    alpha_kernel<<<NB, 128>>>(rw, rb);
    weff_kernel <<<dim3(NB, 28), 256>>>(w);
    conv_kernel <<<dim3(TLEN / TT, COUT / COTILE, NB), 256>>>(x, bias, out);
}

// round 5
// speedup vs baseline: 2.5689x; 2.5689x over previous
#include <cuda_runtime.h>
#include <cuda_bf16.h>
#include <cstdint>

#define NB    32
#define CIN   128
#define TLEN  4096
#define KBR   4
#define COUT  256
#define KS    7
#define PADL  3

// ---------------- device scratch ---------------------------------------------
__device__ float g_pooled[NB * CIN];
__device__ float g_alpha[NB * KBR];
// Weff bf16 split, layout [b][s][co][ci]  (ci contiguous)
__device__ __align__(16) __nv_bfloat16 g_wh[(size_t)NB * KS * COUT * CIN];
__device__ __align__(16) __nv_bfloat16 g_wl[(size_t)NB * KS * COUT * CIN];
// x transposed bf16 split, layout [b][t][ci]  (ci contiguous)
__device__ __align__(16) __nv_bfloat16 g_xh[(size_t)NB * TLEN * CIN];
__device__ __align__(16) __nv_bfloat16 g_xl[(size_t)NB * TLEN * CIN];

// ---------------- PTX helpers --------------------------------------------------
__device__ __forceinline__ uint32_t smem_to_u32(const void* p) {
    uint32_t a;
    asm("{ .reg .u64 t; cvta.to.shared.u64 t, %1; cvt.u32.u64 %0, t; }"
        : "=r"(a) : "l"(p));
    return a;
}
__device__ __forceinline__ void ldsm_x4(uint32_t& r0, uint32_t& r1,
                                        uint32_t& r2, uint32_t& r3, uint32_t addr) {
    asm volatile("ldmatrix.sync.aligned.m8n8.x4.shared.b16 {%0,%1,%2,%3}, [%4];"
                 : "=r"(r0), "=r"(r1), "=r"(r2), "=r"(r3) : "r"(addr));
}
__device__ __forceinline__ void mma_bf16(float* d, const uint32_t* a,
                                         uint32_t b0, uint32_t b1) {
    asm volatile("mma.sync.aligned.m16n8k16.row.col.f32.bf16.bf16.f32 "
                 "{%0,%1,%2,%3}, {%4,%5,%6,%7}, {%8,%9}, {%0,%1,%2,%3};"
                 : "+f"(d[0]), "+f"(d[1]), "+f"(d[2]), "+f"(d[3])
                 : "r"(a[0]), "r"(a[1]), "r"(a[2]), "r"(a[3]), "r"(b0), "r"(b1));
}
#define CP_ASYNC16(dst, src) \
    asm volatile("cp.async.cg.shared.global [%0], [%1], 16;" :: "r"(dst), "l"(src))
#define CP_COMMIT() asm volatile("cp.async.commit_group;" ::: "memory")
#define CP_WAIT0()  asm volatile("cp.async.wait_group 0;" ::: "memory")

// ---------------- smem layout ---------------------------------------------------
// A chunk tile: 128 co rows x 64 ci (128B/row) = 16KB. 4 tiles: [buf][h]
// B tile: 136 t rows x 128 ci (256B/row) = 34816B. 2 tiles (hi, lo)
#define A_TILE    16384
#define B_OFF     65536
#define B_TILE    34816
#define SMEM_TOTAL (B_OFF + 2 * B_TILE)   // 135168

__device__ __forceinline__ uint32_t swzA(int row, int c16) {   // 8 chunks/row
    return (uint32_t)(row * 128 + (((c16 ^ row) & 7) << 4));
}
__device__ __forceinline__ uint32_t swzB(int row, int c16) {   // 16 chunks/row
    return (uint32_t)(row * 256 + (((c16 & 8) | ((c16 ^ row) & 7)) << 4));
}

// ---------------- 1) pooled mean -----------------------------------------------
__global__ void pool_kernel(const float* __restrict__ x) {
    int row = blockIdx.x;
    const float4* xr = reinterpret_cast<const float4*>(x + (size_t)row * TLEN);
    float s = 0.f;
    for (int i = threadIdx.x; i < TLEN / 4; i += blockDim.x) {
        float4 v = xr[i];
        s += (v.x + v.y) + (v.z + v.w);
    }
    __shared__ float sm[8];
    int lane = threadIdx.x & 31, wrp = threadIdx.x >> 5;
    #pragma unroll
    for (int o = 16; o; o >>= 1) s += __shfl_down_sync(0xffffffffu, s, o);
    if (lane == 0) sm[wrp] = s;
    __syncthreads();
    if (threadIdx.x == 0) {
        float v = 0.f;
        for (int i = 0; i < (int)(blockDim.x >> 5); i++) v += sm[i];
        g_pooled[row] = v * (1.0f / TLEN);
    }
}

// ---------------- 2) routing softmax --------------------------------------------
__global__ void alpha_kernel(const float* __restrict__ rw,
                             const float* __restrict__ rb) {
    int b = blockIdx.x, tid = threadIdx.x;
    float p = g_pooled[b * CIN + tid];
    __shared__ float part[KBR][4];
    int lane = tid & 31, wrp = tid >> 5;
    #pragma unroll
    for (int k = 0; k < KBR; k++) {
        float v = p * rw[k * CIN + tid];
        #pragma unroll
        for (int o = 16; o; o >>= 1) v += __shfl_down_sync(0xffffffffu, v, o);
        if (lane == 0) part[k][wrp] = v;
    }
    __syncthreads();
    if (tid == 0) {
        float sc[KBR], m = -1e30f;
        #pragma unroll
        for (int k = 0; k < KBR; k++) {
            sc[k] = part[k][0] + part[k][1] + part[k][2] + part[k][3] + rb[k];
            m = fmaxf(m, sc[k]);
        }
        float den = 0.f;
        #pragma unroll
        for (int k = 0; k < KBR; k++) { sc[k] = __expf(sc[k] - m); den += sc[k]; }
        float inv = 1.0f / den;
        #pragma unroll
        for (int k = 0; k < KBR; k++) g_alpha[b * KBR + k] = sc[k] * inv;
    }
}

// ---------------- 3) Weff -> bf16 split, layout [b][s][co][ci] -------------------
__global__ void weff_kernel(const float* __restrict__ w) {
    int b = blockIdx.x, co = blockIdx.y;
    __shared__ float sm[CIN * KS];
    float a0 = g_alpha[b * KBR + 0], a1 = g_alpha[b * KBR + 1];
    float a2 = g_alpha[b * KBR + 2], a3 = g_alpha[b * KBR + 3];
    const size_t kst = (size_t)COUT * CIN * KS;
    const float* wp = w + (size_t)co * CIN * KS;
    for (int i = threadIdx.x; i < CIN * KS; i += blockDim.x)
        sm[i] = a0 * wp[i] + a1 * wp[i + kst] + a2 * wp[i + 2 * kst] + a3 * wp[i + 3 * kst];
    __syncthreads();
    for (int i = threadIdx.x; i < CIN * KS; i += blockDim.x) {
        int s = i >> 7, ci = i & 127;
        float v = sm[ci * KS + s];
        __nv_bfloat16 hi = __float2bfloat16(v);
        float lo = v - __bfloat162float(hi);
        size_t o = (((size_t)b * KS + s) * COUT + co) * CIN + ci;
        g_wh[o] = hi;
        g_wl[o] = __float2bfloat16(lo);
    }
}

// ---------------- 4) x transpose + bf16 split: [b][t][ci] ------------------------
__global__ void xt_kernel(const float* __restrict__ x) {
    __shared__ float tile[32][33];
    int b = blockIdx.z;
    int t0 = blockIdx.x * 32, c0 = blockIdx.y * 32;
    int tx = threadIdx.x, ty = threadIdx.y;        // (32, 8)
    const float* xb = x + ((size_t)b * CIN + c0) * TLEN + t0;
    for (int r = ty; r < 32; r += 8)
        tile[r][tx] = xb[(size_t)r * TLEN + tx];
    __syncthreads();
    for (int tt = ty; tt < 32; tt += 8) {
        float v = tile[tx][tt];
        __nv_bfloat16 hi = __float2bfloat16(v);
        size_t o = ((size_t)b * TLEN + t0 + tt) * CIN + c0 + tx;
        g_xh[o] = hi;
        g_xl[o] = __float2bfloat16(v - __bfloat162float(hi));
    }
}

// ---------------- 5) routed conv via mma.sync (HMMA, bf16 3-product split) -------
// Per CTA: b, co-tile 128, t-tile 128. 8 warps = 4(m) x 2(n); warp tile 32co x 64t.
// K loop: 14 stages = 7 taps x 2 ci-chunks(64). B resident; A cp.async double-buffered.
__global__ __launch_bounds__(256, 1)
void conv_hmma_kernel(const float* __restrict__ bias, float* __restrict__ out) {
    extern __shared__ char smem[];
    uint32_t sbase = smem_to_u32(smem);
    int tid = threadIdx.x, wid = tid >> 5, lane = tid & 31;
    int t0  = blockIdx.x * 128;
    int co0 = blockIdx.y * 128;
    int b   = blockIdx.z;
    int co_w = (wid >> 1) * 32;      // warp co offset within tile
    int t_w  = (wid & 1) * 64;       // warp t offset within tile

    // per-lane ldmatrix address components
    int a_row = lane & 15;           // A: row within 16
    int a_c   = lane >> 4;           // A: chunk select (k half)
    int b_row = lane & 7;            // B: row within 8
    int b_c   = (lane >> 3) & 1;     // B: chunk select (k half)
    uint32_t b_half = (uint32_t)(lane >> 4) * B_TILE;  // hi/lo tile select

    const __nv_bfloat16* wh_b = g_wh + (((size_t)b * KS) * COUT + co0) * CIN;
    const __nv_bfloat16* wl_b = g_wl + (((size_t)b * KS) * COUT + co0) * CIN;

    // ---- stage B once: rows 0..135 -> t = t0 + row - 3, hi & lo -----------------
    for (int idx = tid; idx < 2 * 136 * 16; idx += 256) {
        int h   = idx / (136 * 16);
        int rem = idx - h * (136 * 16);
        int row = rem >> 4, c16 = rem & 15;
        int tg  = t0 + row - PADL;
        uint4 v = make_uint4(0u, 0u, 0u, 0u);
        if (tg >= 0 && tg < TLEN) {
            size_t src = ((size_t)b * TLEN + tg) * CIN + c16 * 8;
            v = h ? *reinterpret_cast<const uint4*>(g_xl + src)
                  : *reinterpret_cast<const uint4*>(g_xh + src);
        }
        *reinterpret_cast<uint4*>(smem + B_OFF + h * B_TILE + swzB(row, c16)) = v;
    }

    // ---- A stage issue helper (cp.async, 8 chunks per thread) -------------------
    // stage st: s = st>>1, cc = st&1 ; tile rows=co(128) x 64 ci, hi & lo
    auto issueA = [&](int st, int buf) {
        int s = st >> 1, cc = st & 1;
        #pragma unroll
        for (int i = 0; i < 8; i++) {
            int idx = tid + i * 256;             // 0..2047
            int h   = idx >> 10;
            int rem = idx & 1023;
            int row = rem >> 3, c16 = rem & 7;
            const __nv_bfloat16* src = (h ? wl_b : wh_b)
                + ((size_t)s * COUT + row) * CIN + cc * 64 + c16 * 8;
            uint32_t dst = sbase + (uint32_t)(buf * 2 + h) * A_TILE + swzA(row, c16);
            CP_ASYNC16(dst, src);
        }
        CP_COMMIT();
    };

    issueA(0, 0);

    float acc[2][8][4];
    #pragma unroll
    for (int m = 0; m < 2; m++)
        #pragma unroll
        for (int j = 0; j < 8; j++)
            #pragma unroll
            for (int q = 0; q < 4; q++) acc[m][j][q] = 0.f;

    for (int st = 0; st < 14; st++) {
        CP_WAIT0();
        __syncthreads();                 // stage st visible; prev mma done by all warps
        if (st + 1 < 14) issueA(st + 1, (st + 1) & 1);

        int s  = st >> 1;
        int cc = st & 1;                 // ci half: B chunk base = cc*8
        uint32_t aHi = sbase + (uint32_t)((st & 1) * 2 + 0) * A_TILE;
        uint32_t aLo = sbase + (uint32_t)((st & 1) * 2 + 1) * A_TILE;

        #pragma unroll
        for (int kk = 0; kk < 4; kk++) {
            uint32_t ah[2][4], al[2][4];
            #pragma unroll
            for (int m = 0; m < 2; m++) {
                uint32_t off = swzA(co_w + m * 16 + a_row, kk * 2 + a_c);
                ldsm_x4(ah[m][0], ah[m][1], ah[m][2], ah[m][3], aHi + off);
                ldsm_x4(al[m][0], al[m][1], al[m][2], al[m][3], aLo + off);
            }
            #pragma unroll
            for (int j = 0; j < 8; j++) {
                uint32_t bh0, bh1, bl0, bl1;
                uint32_t baddr = sbase + B_OFF + b_half
                    + swzB(t_w + j * 8 + s + b_row, cc * 8 + kk * 2 + b_c);
                ldsm_x4(bh0, bh1, bl0, bl1, baddr);
                #pragma unroll
                for (int m = 0; m < 2; m++) {
                    mma_bf16(acc[m][j], ah[m], bh0, bh1);   // hi*hi
                    mma_bf16(acc[m][j], ah[m], bl0, bl1);   // hi*lo
                    mma_bf16(acc[m][j], al[m], bh0, bh1);   // lo*hi
                }
            }
        }
    }

    // ---- epilogue: bias_eff + direct stores (float2) ----------------------------
    float a0 = g_alpha[b * KBR + 0], a1 = g_alpha[b * KBR + 1];
    float a2 = g_alpha[b * KBR + 2], a3 = g_alpha[b * KBR + 3];
    int qr = lane >> 2, qc = (lane & 3) * 2;
    #pragma unroll
    for (int m = 0; m < 2; m++) {
        int coA = co0 + co_w + m * 16 + qr;
        int coB = coA + 8;
        float beA = a0 * bias[coA] + a1 * bias[COUT + coA]
                  + a2 * bias[2 * COUT + coA] + a3 * bias[3 * COUT + coA];
        float beB = a0 * bias[coB] + a1 * bias[COUT + coB]
                  + a2 * bias[2 * COUT + coB] + a3 * bias[3 * COUT + coB];
        float* pA = out + ((size_t)b * COUT + coA) * TLEN + t0 + t_w + qc;
        float* pB = out + ((size_t)b * COUT + coB) * TLEN + t0 + t_w + qc;
        #pragma unroll
        for (int j = 0; j < 8; j++) {
            float2 vA = make_float2(acc[m][j][0] + beA, acc[m][j][1] + beA);
            float2 vB = make_float2(acc[m][j][2] + beB, acc[m][j][3] + beB);
            *reinterpret_cast<float2*>(pA + j * 8) = vA;
            *reinterpret_cast<float2*>(pB + j * 8) = vB;
        }
    }
}

// ---------------- launch ----------------------------------------------------------
extern "C" void kernel_launch(void* const* d_in, const int* in_sizes, int n_in,
                              void* d_out, int out_size) {
    const float* x    = (const float*)d_in[0];   // [32,128,4096]
    const float* w    = (const float*)d_in[1];   // [4,256,128,7]
    const float* bias = (const float*)d_in[2];   // [4,256]
    const float* rw   = (const float*)d_in[3];   // [4,128]
    const float* rb   = (const float*)d_in[4];   // [4]
    float* out = (float*)d_out;                  // [32,256,4096]

    pool_kernel <<<NB * CIN, 256>>>(x);
    alpha_kernel<<<NB, 128>>>(rw, rb);
    weff_kernel <<<dim3(NB, COUT), 256>>>(w);
    xt_kernel   <<<dim3(TLEN / 32, CIN / 32, NB), dim3(32, 8)>>>(x);

    cudaFuncSetAttribute(conv_hmma_kernel,
                         cudaFuncAttributeMaxDynamicSharedMemorySize, SMEM_TOTAL);
    conv_hmma_kernel<<<dim3(TLEN / 128, COUT / 128, NB), 256, SMEM_TOTAL>>>(bias, out);
}

// round 6
// speedup vs baseline: 6.0200x; 2.3434x over previous
#include <cuda_runtime.h>
#include <cuda_fp16.h>
#include <cstdint>

#define NB    32
#define CIN   128
#define TLEN  4096
#define KBR   4
#define COUT  256
#define KS    7
#define PADL  3

// ---------------- device scratch ---------------------------------------------
__device__ float g_pooled[NB * CIN];
__device__ float g_alpha[NB * KBR];
// Weff fp16, layout [b][s][co][ci]  (ci contiguous)
__device__ __align__(16) __half g_wh[(size_t)NB * KS * COUT * CIN];
// x transposed fp16, layout [b][t][ci]  (ci contiguous)
__device__ __align__(16) __half g_xh[(size_t)NB * TLEN * CIN];

// ---------------- PTX helpers --------------------------------------------------
__device__ __forceinline__ uint32_t smem_to_u32(const void* p) {
    uint32_t a;
    asm("{ .reg .u64 t; cvta.to.shared.u64 t, %1; cvt.u32.u64 %0, t; }"
        : "=r"(a) : "l"(p));
    return a;
}
__device__ __forceinline__ void ldsm_x4(uint32_t& r0, uint32_t& r1,
                                        uint32_t& r2, uint32_t& r3, uint32_t addr) {
    asm volatile("ldmatrix.sync.aligned.m8n8.x4.shared.b16 {%0,%1,%2,%3}, [%4];"
                 : "=r"(r0), "=r"(r1), "=r"(r2), "=r"(r3) : "r"(addr));
}
__device__ __forceinline__ void mma_f16(float* d, const uint32_t* a,
                                        uint32_t b0, uint32_t b1) {
    asm volatile("mma.sync.aligned.m16n8k16.row.col.f32.f16.f16.f32 "
                 "{%0,%1,%2,%3}, {%4,%5,%6,%7}, {%8,%9}, {%0,%1,%2,%3};"
                 : "+f"(d[0]), "+f"(d[1]), "+f"(d[2]), "+f"(d[3])
                 : "r"(a[0]), "r"(a[1]), "r"(a[2]), "r"(a[3]), "r"(b0), "r"(b1));
}
#define CP_ASYNC16(dst, src) \
    asm volatile("cp.async.cg.shared.global [%0], [%1], 16;" :: "r"(dst), "l"(src))
#define CP_COMMIT() asm volatile("cp.async.commit_group;" ::: "memory")
#define CP_WAIT0()  asm volatile("cp.async.wait_group 0;" ::: "memory")

// ---------------- smem layout ---------------------------------------------------
// A chunk tile: 128 co rows x 64 ci fp16 (128B/row) = 16KB. 2 buffers.
// B tile: 136 t rows x 128 ci fp16 (256B/row) = 34816B. resident.
#define A_TILE    16384
#define B_OFF     32768
#define B_TILE    34816
#define SMEM_TOTAL (B_OFF + B_TILE)   // 67584 -> occupancy 2

__device__ __forceinline__ uint32_t swzA(int row, int c16) {   // 8 chunks/row
    return (uint32_t)(row * 128 + (((c16 ^ row) & 7) << 4));
}
__device__ __forceinline__ uint32_t swzB(int row, int c16) {   // 16 chunks/row
    return (uint32_t)(row * 256 + (((c16 & 8) | ((c16 ^ row) & 7)) << 4));
}

// ---------------- 1) pooled mean -----------------------------------------------
__global__ void pool_kernel(const float* __restrict__ x) {
    int row = blockIdx.x;
    const float4* xr = reinterpret_cast<const float4*>(x + (size_t)row * TLEN);
    float s = 0.f;
    for (int i = threadIdx.x; i < TLEN / 4; i += blockDim.x) {
        float4 v = xr[i];
        s += (v.x + v.y) + (v.z + v.w);
    }
    __shared__ float sm[8];
    int lane = threadIdx.x & 31, wrp = threadIdx.x >> 5;
    #pragma unroll
    for (int o = 16; o; o >>= 1) s += __shfl_down_sync(0xffffffffu, s, o);
    if (lane == 0) sm[wrp] = s;
    __syncthreads();
    if (threadIdx.x == 0) {
        float v = 0.f;
        for (int i = 0; i < (int)(blockDim.x >> 5); i++) v += sm[i];
        g_pooled[row] = v * (1.0f / TLEN);
    }
}

// ---------------- 2) routing softmax --------------------------------------------
__global__ void alpha_kernel(const float* __restrict__ rw,
                             const float* __restrict__ rb) {
    int b = blockIdx.x, tid = threadIdx.x;
    float p = g_pooled[b * CIN + tid];
    __shared__ float part[KBR][4];
    int lane = tid & 31, wrp = tid >> 5;
    #pragma unroll
    for (int k = 0; k < KBR; k++) {
        float v = p * rw[k * CIN + tid];
        #pragma unroll
        for (int o = 16; o; o >>= 1) v += __shfl_down_sync(0xffffffffu, v, o);
        if (lane == 0) part[k][wrp] = v;
    }
    __syncthreads();
    if (tid == 0) {
        float sc[KBR], m = -1e30f;
        #pragma unroll
        for (int k = 0; k < KBR; k++) {
            sc[k] = part[k][0] + part[k][1] + part[k][2] + part[k][3] + rb[k];
            m = fmaxf(m, sc[k]);
        }
        float den = 0.f;
        #pragma unroll
        for (int k = 0; k < KBR; k++) { sc[k] = __expf(sc[k] - m); den += sc[k]; }
        float inv = 1.0f / den;
        #pragma unroll
        for (int k = 0; k < KBR; k++) g_alpha[b * KBR + k] = sc[k] * inv;
    }
}

// ---------------- 3) Weff -> fp16, layout [b][s][co][ci] -------------------------
__global__ void weff_kernel(const float* __restrict__ w) {
    int b = blockIdx.x, co = blockIdx.y;
    __shared__ float sm[CIN * KS];
    float a0 = g_alpha[b * KBR + 0], a1 = g_alpha[b * KBR + 1];
    float a2 = g_alpha[b * KBR + 2], a3 = g_alpha[b * KBR + 3];
    const size_t kst = (size_t)COUT * CIN * KS;
    const float* wp = w + (size_t)co * CIN * KS;
    for (int i = threadIdx.x; i < CIN * KS; i += blockDim.x)
        sm[i] = a0 * wp[i] + a1 * wp[i + kst] + a2 * wp[i + 2 * kst] + a3 * wp[i + 3 * kst];
    __syncthreads();
    for (int i = threadIdx.x; i < CIN * KS; i += blockDim.x) {
        int s = i >> 7, ci = i & 127;
        size_t o = (((size_t)b * KS + s) * COUT + co) * CIN + ci;
        g_wh[o] = __float2half(sm[ci * KS + s]);
    }
}

// ---------------- 4) x transpose -> fp16: [b][t][ci] -----------------------------
__global__ void xt_kernel(const float* __restrict__ x) {
    __shared__ float tile[32][33];
    int b = blockIdx.z;
    int t0 = blockIdx.x * 32, c0 = blockIdx.y * 32;
    int tx = threadIdx.x, ty = threadIdx.y;        // (32, 8)
    const float* xb = x + ((size_t)b * CIN + c0) * TLEN + t0;
    for (int r = ty; r < 32; r += 8)
        tile[r][tx] = xb[(size_t)r * TLEN + tx];
    __syncthreads();
    for (int tt = ty; tt < 32; tt += 8) {
        size_t o = ((size_t)b * TLEN + t0 + tt) * CIN + c0 + tx;
        g_xh[o] = __float2half(tile[tx][tt]);
    }
}

// ---------------- 5) routed conv via mma.sync fp16 single-product ----------------
// Per CTA: b, co-tile 128, t-tile 128. 8 warps = 4(m) x 2(n); warp tile 32co x 64t.
// K: 14 stages = 7 taps x 2 ci-chunks(64). B resident; A cp.async double-buffered.
__global__ __launch_bounds__(256, 2)
void conv_hmma_kernel(const float* __restrict__ bias, float* __restrict__ out) {
    extern __shared__ char smem[];
    uint32_t sbase = smem_to_u32(smem);
    int tid = threadIdx.x, wid = tid >> 5, lane = tid & 31;
    int t0  = blockIdx.x * 128;
    int co0 = blockIdx.y * 128;
    int b   = blockIdx.z;
    int co_w = (wid >> 1) * 32;      // warp co offset within tile
    int t_w  = (wid & 1) * 64;       // warp t offset within tile

    // per-lane ldmatrix address components
    int a_row = lane & 15;           // A: row within 16
    int a_c   = lane >> 4;           // A: chunk select within k16
    int b_row = lane & 7;            // B: row within 8
    int b_g   = lane >> 3;           // B: chunk select 0..3 (covers 2 k16 steps)

    const __half* wh_b = g_wh + (((size_t)b * KS) * COUT + co0) * CIN;

    // ---- stage B once: rows 0..135 -> t = t0 + row - 3 --------------------------
    for (int idx = tid; idx < 136 * 16; idx += 256) {
        int row = idx >> 4, c16 = idx & 15;
        int tg  = t0 + row - PADL;
        uint4 v = make_uint4(0u, 0u, 0u, 0u);
        if (tg >= 0 && tg < TLEN)
            v = *reinterpret_cast<const uint4*>(
                g_xh + ((size_t)b * TLEN + tg) * CIN + c16 * 8);
        *reinterpret_cast<uint4*>(smem + B_OFF + swzB(row, c16)) = v;
    }

    // ---- A stage issue (cp.async, 4 chunks per thread): 128 co x 64 ci ----------
    auto issueA = [&](int st, int buf) {
        int s = st >> 1, cc = st & 1;
        #pragma unroll
        for (int i = 0; i < 4; i++) {
            int idx = tid + i * 256;             // 0..1023
            int row = idx >> 3, c16 = idx & 7;
            const __half* src = wh_b + ((size_t)s * COUT + row) * CIN + cc * 64 + c16 * 8;
            CP_ASYNC16(sbase + (uint32_t)buf * A_TILE + swzA(row, c16), src);
        }
        CP_COMMIT();
    };

    issueA(0, 0);

    float acc[2][8][4];
    #pragma unroll
    for (int m = 0; m < 2; m++)
        #pragma unroll
        for (int j = 0; j < 8; j++)
            #pragma unroll
            for (int q = 0; q < 4; q++) acc[m][j][q] = 0.f;

    for (int st = 0; st < 14; st++) {
        CP_WAIT0();
        __syncthreads();                 // stage st visible; prev mma drained
        if (st + 1 < 14) issueA(st + 1, (st + 1) & 1);

        int s  = st >> 1;
        int cc = st & 1;                 // ci half: B chunk base = cc*8
        uint32_t aBuf = sbase + (uint32_t)(st & 1) * A_TILE;

        #pragma unroll
        for (int q = 0; q < 2; q++) {    // k16 pair: kk = 2q, 2q+1
            // A fragments: [m][kk in pair][4 regs]
            uint32_t a[2][2][4];
            #pragma unroll
            for (int m = 0; m < 2; m++)
                #pragma unroll
                for (int kx = 0; kx < 2; kx++) {
                    uint32_t off = swzA(co_w + m * 16 + a_row, (q * 2 + kx) * 2 + a_c);
                    ldsm_x4(a[m][kx][0], a[m][kx][1], a[m][kx][2], a[m][kx][3],
                            aBuf + off);
                }
            #pragma unroll
            for (int j = 0; j < 8; j++) {
                // one x4 covers both k16 steps of the pair: chunks cc*8 + q*4 + b_g
                uint32_t b0, b1, b2, b3;
                uint32_t baddr = sbase + B_OFF
                    + swzB(t_w + j * 8 + s + b_row, cc * 8 + q * 4 + b_g);
                ldsm_x4(b0, b1, b2, b3, baddr);
                #pragma unroll
                for (int m = 0; m < 2; m++) {
                    mma_f16(acc[m][j], a[m][0], b0, b1);
                    mma_f16(acc[m][j], a[m][1], b2, b3);
                }
            }
        }
    }

    // ---- epilogue: bias_eff + direct stores (float2) ----------------------------
    float a0 = g_alpha[b * KBR + 0], a1 = g_alpha[b * KBR + 1];
    float a2 = g_alpha[b * KBR + 2], a3 = g_alpha[b * KBR + 3];
    int qr = lane >> 2, qc = (lane & 3) * 2;
    #pragma unroll
    for (int m = 0; m < 2; m++) {
        int coA = co0 + co_w + m * 16 + qr;
        int coB = coA + 8;
        float beA = a0 * bias[coA] + a1 * bias[COUT + coA]
                  + a2 * bias[2 * COUT + coA] + a3 * bias[3 * COUT + coA];
        float beB = a0 * bias[coB] + a1 * bias[COUT + coB]
                  + a2 * bias[2 * COUT + coB] + a3 * bias[3 * COUT + coB];
        float* pA = out + ((size_t)b * COUT + coA) * TLEN + t0 + t_w + qc;
        float* pB = out + ((size_t)b * COUT + coB) * TLEN + t0 + t_w + qc;
        #pragma unroll
        for (int j = 0; j < 8; j++) {
            float2 vA = make_float2(acc[m][j][0] + beA, acc[m][j][1] + beA);
            float2 vB = make_float2(acc[m][j][2] + beB, acc[m][j][3] + beB);
            *reinterpret_cast<float2*>(pA + j * 8) = vA;
            *reinterpret_cast<float2*>(pB + j * 8) = vB;
        }
    }
}

// ---------------- launch ----------------------------------------------------------
extern "C" void kernel_launch(void* const* d_in, const int* in_sizes, int n_in,
                              void* d_out, int out_size) {
    const float* x    = (const float*)d_in[0];   // [32,128,4096]
    const float* w    = (const float*)d_in[1];   // [4,256,128,7]
    const float* bias = (const float*)d_in[2];   // [4,256]
    const float* rw   = (const float*)d_in[3];   // [4,128]
    const float* rb   = (const float*)d_in[4];   // [4]
    float* out = (float*)d_out;                  // [32,256,4096]

    pool_kernel <<<NB * CIN, 256>>>(x);
    alpha_kernel<<<NB, 128>>>(rw, rb);
    weff_kernel <<<dim3(NB, COUT), 256>>>(w);
    xt_kernel   <<<dim3(TLEN / 32, CIN / 32, NB), dim3(32, 8)>>>(x);

    cudaFuncSetAttribute(conv_hmma_kernel,
                         cudaFuncAttributeMaxDynamicSharedMemorySize, SMEM_TOTAL);
    conv_hmma_kernel<<<dim3(TLEN / 128, COUT / 128, NB), 256, SMEM_TOTAL>>>(bias, out);
}

// round 7
// speedup vs baseline: 7.1501x; 1.1877x over previous
#include <cuda_runtime.h>
#include <cuda_fp16.h>
#include <cstdint>

#define NB    32
#define CIN   128
#define TLEN  4096
#define KBR   4
#define COUT  256
#define KS    7
#define PADL  3

// ---------------- device scratch ---------------------------------------------
__device__ float g_pooled4[4][NB * CIN];     // 4 deterministic t-quarter partials
__device__ float g_alpha[NB * KBR];
// Weff fp16, layout [b][s][co][ci]  (ci contiguous)
__device__ __align__(16) __half g_wh[(size_t)NB * KS * COUT * CIN];
// x transposed fp16, layout [b][t][ci]  (ci contiguous)
__device__ __align__(16) __half g_xh[(size_t)NB * TLEN * CIN];

// ---------------- PTX helpers --------------------------------------------------
__device__ __forceinline__ uint32_t smem_to_u32(const void* p) {
    uint32_t a;
    asm("{ .reg .u64 t; cvta.to.shared.u64 t, %1; cvt.u32.u64 %0, t; }"
        : "=r"(a) : "l"(p));
    return a;
}
__device__ __forceinline__ void ldsm_x4(uint32_t& r0, uint32_t& r1,
                                        uint32_t& r2, uint32_t& r3, uint32_t addr) {
    asm volatile("ldmatrix.sync.aligned.m8n8.x4.shared.b16 {%0,%1,%2,%3}, [%4];"
                 : "=r"(r0), "=r"(r1), "=r"(r2), "=r"(r3) : "r"(addr));
}
__device__ __forceinline__ void mma_f16(float* d, const uint32_t* a,
                                        uint32_t b0, uint32_t b1) {
    asm volatile("mma.sync.aligned.m16n8k16.row.col.f32.f16.f16.f32 "
                 "{%0,%1,%2,%3}, {%4,%5,%6,%7}, {%8,%9}, {%0,%1,%2,%3};"
                 : "+f"(d[0]), "+f"(d[1]), "+f"(d[2]), "+f"(d[3])
                 : "r"(a[0]), "r"(a[1]), "r"(a[2]), "r"(a[3]), "r"(b0), "r"(b1));
}
#define CP_ASYNC16(dst, src) \
    asm volatile("cp.async.cg.shared.global [%0], [%1], 16;" :: "r"(dst), "l"(src))
#define CP_COMMIT() asm volatile("cp.async.commit_group;" ::: "memory")
#define CP_WAIT0()  asm volatile("cp.async.wait_group 0;" ::: "memory")

// ---------------- conv smem layout ----------------------------------------------
#define A_TILE    16384
#define B_OFF     32768
#define B_TILE    34816
#define SMEM_TOTAL (B_OFF + B_TILE)   // 67584 -> occupancy 2

__device__ __forceinline__ uint32_t swzA(int row, int c16) {   // 8 chunks/row
    return (uint32_t)(row * 128 + (((c16 ^ row) & 7) << 4));
}
__device__ __forceinline__ uint32_t swzB(int row, int c16) {   // 16 chunks/row
    return (uint32_t)(row * 256 + (((c16 & 8) | ((c16 ^ row) & 7)) << 4));
}

// ---------------- 1) fused x-transpose + fp16 + pooled partials -----------------
// grid (4 t-quarters, 4 ci-chunks, NB), block 256.
// Per block: slab x[b][ci0:ci0+32][tq*1024 : +1024]; 16 sub-tiles of 32ci x 64t.
__global__ __launch_bounds__(256) void xt2_kernel(const float* __restrict__ x) {
    __shared__ float tile[2][32][65];
    int b = blockIdx.z, ci0 = blockIdx.y * 32, tq = blockIdx.x;
    int tid = threadIdx.x;
    int rowr = tid >> 3, l8 = tid & 7;            // load: 8 threads per ci row
    int ts = tid >> 2, ci8 = (tid & 3) * 8;       // store: 4 threads per t row
    const float* src = x + ((size_t)(b * CIN + ci0 + rowr)) * TLEN
                         + tq * 1024 + l8 * 8;
    float psum = 0.f;
    for (int sub = 0; sub < 16; sub++) {
        float4 v0 = *reinterpret_cast<const float4*>(src + sub * 64);
        float4 v1 = *reinterpret_cast<const float4*>(src + sub * 64 + 4);
        psum += (v0.x + v0.y) + (v0.z + v0.w) + (v1.x + v1.y) + (v1.z + v1.w);
        float* tr = &tile[sub & 1][rowr][l8 * 8];
        tr[0] = v0.x; tr[1] = v0.y; tr[2] = v0.z; tr[3] = v0.w;
        tr[4] = v1.x; tr[5] = v1.y; tr[6] = v1.z; tr[7] = v1.w;
        __syncthreads();
        __half2 h[4];
        #pragma unroll
        for (int i = 0; i < 4; i++)
            h[i] = __floats2half2_rn(tile[sub & 1][ci8 + 2 * i][ts],
                                     tile[sub & 1][ci8 + 2 * i + 1][ts]);
        int t = tq * 1024 + sub * 64 + ts;
        *reinterpret_cast<uint4*>(g_xh + ((size_t)b * TLEN + t) * CIN + ci0 + ci8)
            = *reinterpret_cast<uint4*>(h);
    }
    #pragma unroll
    for (int o = 4; o; o >>= 1) psum += __shfl_down_sync(0xffffffffu, psum, o, 8);
    if (l8 == 0) g_pooled4[tq][b * CIN + ci0 + rowr] = psum * (1.0f / TLEN);
}

// ---------------- 2) routing softmax ----------------------------------------------
__global__ void alpha_kernel(const float* __restrict__ rw,
                             const float* __restrict__ rb) {
    int b = blockIdx.x, tid = threadIdx.x;     // 128 threads
    int row = b * CIN + tid;
    float p = g_pooled4[0][row] + g_pooled4[1][row]
            + g_pooled4[2][row] + g_pooled4[3][row];
    __shared__ float part[KBR][4];
    int lane = tid & 31, wrp = tid >> 5;
    #pragma unroll
    for (int k = 0; k < KBR; k++) {
        float v = p * rw[k * CIN + tid];
        #pragma unroll
        for (int o = 16; o; o >>= 1) v += __shfl_down_sync(0xffffffffu, v, o);
        if (lane == 0) part[k][wrp] = v;
    }
    __syncthreads();
    if (tid == 0) {
        float sc[KBR], m = -1e30f;
        #pragma unroll
        for (int k = 0; k < KBR; k++) {
            sc[k] = part[k][0] + part[k][1] + part[k][2] + part[k][3] + rb[k];
            m = fmaxf(m, sc[k]);
        }
        float den = 0.f;
        #pragma unroll
        for (int k = 0; k < KBR; k++) { sc[k] = __expf(sc[k] - m); den += sc[k]; }
        float inv = 1.0f / den;
        #pragma unroll
        for (int k = 0; k < KBR; k++) g_alpha[b * KBR + k] = sc[k] * inv;
    }
}

// ---------------- 3) Weff -> fp16: stage w[:,co] once, loop 16 batches -----------
// grid (COUT, 2), block 256.
__global__ __launch_bounds__(256) void weff2_kernel(const float* __restrict__ w) {
    __shared__ float wsm[KBR][CIN * KS];       // 14KB
    int co = blockIdx.x, bh = blockIdx.y;
    int tid = threadIdx.x;
    for (int i = tid; i < KBR * CIN * KS; i += 256) {
        int k = i / (CIN * KS), j = i - k * (CIN * KS);
        wsm[k][j] = w[((size_t)k * COUT + co) * (CIN * KS) + j];
    }
    __syncthreads();
    for (int b = bh * 16; b < bh * 16 + 16; b++) {
        float a0 = g_alpha[b * KBR + 0], a1 = g_alpha[b * KBR + 1];
        float a2 = g_alpha[b * KBR + 2], a3 = g_alpha[b * KBR + 3];
        for (int i = tid; i < 448; i += 256) {
            int s = i >> 6, c = i & 63;
            int j0 = (2 * c) * KS + s, j1 = j0 + KS;
            float v0 = a0 * wsm[0][j0] + a1 * wsm[1][j0]
                     + a2 * wsm[2][j0] + a3 * wsm[3][j0];
            float v1 = a0 * wsm[0][j1] + a1 * wsm[1][j1]
                     + a2 * wsm[2][j1] + a3 * wsm[3][j1];
            *reinterpret_cast<__half2*>(
                g_wh + (((size_t)b * KS + s) * COUT + co) * CIN + 2 * c)
                = __floats2half2_rn(v0, v1);
        }
    }
}

// ---------------- 4) routed conv via mma.sync fp16 single-product ----------------
// Per CTA: b, co-tile 128, t-tile 128. 8 warps = 4(m) x 2(n); warp tile 32co x 64t.
// K: 14 stages = 7 taps x 2 ci-chunks(64). B resident; A cp.async double-buffered.
__global__ __launch_bounds__(256, 2)
void conv_hmma_kernel(const float* __restrict__ bias, float* __restrict__ out) {
    extern __shared__ char smem[];
    uint32_t sbase = smem_to_u32(smem);
    int tid = threadIdx.x, wid = tid >> 5, lane = tid & 31;
    int t0  = blockIdx.x * 128;
    int co0 = blockIdx.y * 128;
    int b   = blockIdx.z;
    int co_w = (wid >> 1) * 32;      // warp co offset within tile
    int t_w  = (wid & 1) * 64;       // warp t offset within tile

    int a_row = lane & 15;           // A: row within 16
    int a_c   = lane >> 4;           // A: chunk select within k16
    int b_row = lane & 7;            // B: row within 8
    int b_g   = lane >> 3;           // B: chunk select 0..3 (covers 2 k16 steps)

    const __half* wh_b = g_wh + (((size_t)b * KS) * COUT + co0) * CIN;

    // ---- stage B once: rows 0..135 -> t = t0 + row - 3 --------------------------
    for (int idx = tid; idx < 136 * 16; idx += 256) {
        int row = idx >> 4, c16 = idx & 15;
        int tg  = t0 + row - PADL;
        uint4 v = make_uint4(0u, 0u, 0u, 0u);
        if (tg >= 0 && tg < TLEN)
            v = *reinterpret_cast<const uint4*>(
                g_xh + ((size_t)b * TLEN + tg) * CIN + c16 * 8);
        *reinterpret_cast<uint4*>(smem + B_OFF + swzB(row, c16)) = v;
    }

    // ---- A stage issue (cp.async, 4 chunks per thread): 128 co x 64 ci ----------
    auto issueA = [&](int st, int buf) {
        int s = st >> 1, cc = st & 1;
        #pragma unroll
        for (int i = 0; i < 4; i++) {
            int idx = tid + i * 256;             // 0..1023
            int row = idx >> 3, c16 = idx & 7;
            const __half* src = wh_b + ((size_t)s * COUT + row) * CIN + cc * 64 + c16 * 8;
            CP_ASYNC16(sbase + (uint32_t)buf * A_TILE + swzA(row, c16), src);
        }
        CP_COMMIT();
    };

    issueA(0, 0);

    float acc[2][8][4];
    #pragma unroll
    for (int m = 0; m < 2; m++)
        #pragma unroll
        for (int j = 0; j < 8; j++)
            #pragma unroll
            for (int q = 0; q < 4; q++) acc[m][j][q] = 0.f;

    #pragma unroll 2
    for (int st = 0; st < 14; st++) {
        CP_WAIT0();
        __syncthreads();                 // stage st visible; prev mma drained
        if (st + 1 < 14) issueA(st + 1, (st + 1) & 1);

        int s  = st >> 1;
        int cc = st & 1;                 // ci half: B chunk base = cc*8
        uint32_t aBuf = sbase + (uint32_t)(st & 1) * A_TILE;

        #pragma unroll
        for (int q = 0; q < 2; q++) {    // k16 pair: kk = 2q, 2q+1
            uint32_t a[2][2][4];
            #pragma unroll
            for (int m = 0; m < 2; m++)
                #pragma unroll
                for (int kx = 0; kx < 2; kx++) {
                    uint32_t off = swzA(co_w + m * 16 + a_row, (q * 2 + kx) * 2 + a_c);
                    ldsm_x4(a[m][kx][0], a[m][kx][1], a[m][kx][2], a[m][kx][3],
                            aBuf + off);
                }
            #pragma unroll
            for (int j = 0; j < 8; j++) {
                uint32_t b0, b1, b2, b3;
                uint32_t baddr = sbase + B_OFF
                    + swzB(t_w + j * 8 + s + b_row, cc * 8 + q * 4 + b_g);
                ldsm_x4(b0, b1, b2, b3, baddr);
                #pragma unroll
                for (int m = 0; m < 2; m++) {
                    mma_f16(acc[m][j], a[m][0], b0, b1);
                    mma_f16(acc[m][j], a[m][1], b2, b3);
                }
            }
        }
    }

    // ---- epilogue: bias_eff + direct stores (float2) ----------------------------
    float a0 = g_alpha[b * KBR + 0], a1 = g_alpha[b * KBR + 1];
    float a2 = g_alpha[b * KBR + 2], a3 = g_alpha[b * KBR + 3];
    int qr = lane >> 2, qc = (lane & 3) * 2;
    #pragma unroll
    for (int m = 0; m < 2; m++) {
        int coA = co0 + co_w + m * 16 + qr;
        int coB = coA + 8;
        float beA = a0 * bias[coA] + a1 * bias[COUT + coA]
                  + a2 * bias[2 * COUT + coA] + a3 * bias[3 * COUT + coA];
        float beB = a0 * bias[coB] + a1 * bias[COUT + coB]
                  + a2 * bias[2 * COUT + coB] + a3 * bias[3 * COUT + coB];
        float* pA = out + ((size_t)b * COUT + coA) * TLEN + t0 + t_w + qc;
        float* pB = out + ((size_t)b * COUT + coB) * TLEN + t0 + t_w + qc;
        #pragma unroll
        for (int j = 0; j < 8; j++) {
            float2 vA = make_float2(acc[m][j][0] + beA, acc[m][j][1] + beA);
            float2 vB = make_float2(acc[m][j][2] + beB, acc[m][j][3] + beB);
            *reinterpret_cast<float2*>(pA + j * 8) = vA;
            *reinterpret_cast<float2*>(pB + j * 8) = vB;
        }
    }
}

// ---------------- launch ----------------------------------------------------------
extern "C" void kernel_launch(void* const* d_in, const int* in_sizes, int n_in,
                              void* d_out, int out_size) {
    const float* x    = (const float*)d_in[0];   // [32,128,4096]
    const float* w    = (const float*)d_in[1];   // [4,256,128,7]
    const float* bias = (const float*)d_in[2];   // [4,256]
    const float* rw   = (const float*)d_in[3];   // [4,128]
    const float* rb   = (const float*)d_in[4];   // [4]
    float* out = (float*)d_out;                  // [32,256,4096]

    xt2_kernel  <<<dim3(4, CIN / 32, NB), 256>>>(x);
    alpha_kernel<<<NB, 128>>>(rw, rb);
    weff2_kernel<<<dim3(COUT, 2), 256>>>(w);

    cudaFuncSetAttribute(conv_hmma_kernel,
                         cudaFuncAttributeMaxDynamicSharedMemorySize, SMEM_TOTAL);
    conv_hmma_kernel<<<dim3(TLEN / 128, COUT / 128, NB), 256, SMEM_TOTAL>>>(bias, out);
}